// round 1
// baseline (speedup 1.0000x reference)
#include <cuda_runtime.h>

#define NUM_USERS 100000
#define NUM_ITEMS 50000
#define NUM_EDGES 4000000
#define DIM 64
#define V4_PER_ROW (DIM / 4)   // 16 float4 per embedding row

// ---------------------------------------------------------------------------
// Zero the output buffer (harness poisons it to 0xAA).
// ---------------------------------------------------------------------------
__global__ void zero_kernel(float4* __restrict__ out, int n4) {
    int i = blockIdx.x * blockDim.x + threadIdx.x;
    if (i < n4) out[i] = make_float4(0.f, 0.f, 0.f, 0.f);
}

// Vectorized no-return global reduction (REDG): 1 instruction per 16B.
__device__ __forceinline__ void red_add_v4(float* addr, float4 v) {
    asm volatile("red.global.add.v4.f32 [%0], {%1, %2, %3, %4};"
                 :: "l"(addr), "f"(v.x), "f"(v.y), "f"(v.z), "f"(v.w)
                 : "memory");
}

// ---------------------------------------------------------------------------
// Edge-parallel scatter kernel.
// 16 threads cooperate on one edge; each owns one float4 of the 64-float row.
// Row gathers are fully coalesced (16 lanes x 16B = 256B contiguous).
// Scalar edge loads (norm, u, i) hit the same address across the 16-lane
// group -> single L1 request, broadcast.
// ---------------------------------------------------------------------------
__global__ void __launch_bounds__(256)
lightgcn_edge_kernel(const float4* __restrict__ user_emb,
                     const float4* __restrict__ item_emb,
                     const float*  __restrict__ edge_norm,
                     const int*    __restrict__ u_idx,
                     const int*    __restrict__ i_idx,
                     float*        __restrict__ agg_users,
                     float*        __restrict__ agg_items) {
    const int t    = blockIdx.x * blockDim.x + threadIdx.x;
    const int lane = t & (V4_PER_ROW - 1);           // 0..15: which float4 of the row
    int edge       = t >> 4;
    const int estr = (gridDim.x * blockDim.x) >> 4;  // edge-groups in flight

    for (; edge < NUM_EDGES; edge += estr) {
        const int   u = u_idx[edge];
        const int   i = i_idx[edge];
        const float n = edge_norm[edge];

        // user -> items direction
        float4 uv = user_emb[u * V4_PER_ROW + lane];
        uv.x *= n; uv.y *= n; uv.z *= n; uv.w *= n;
        red_add_v4(agg_items + (i * DIM + lane * 4), uv);

        // item -> users direction
        float4 iv = item_emb[i * V4_PER_ROW + lane];
        iv.x *= n; iv.y *= n; iv.z *= n; iv.w *= n;
        red_add_v4(agg_users + (u * DIM + lane * 4), iv);
    }
}

extern "C" void kernel_launch(void* const* d_in, const int* in_sizes, int n_in,
                              void* d_out, int out_size) {
    const float4* user_emb  = (const float4*)d_in[0];
    const float4* item_emb  = (const float4*)d_in[1];
    const float*  edge_norm = (const float*)d_in[2];
    const int*    u_idx     = (const int*)d_in[3];
    const int*    i_idx     = (const int*)d_in[4];

    float* out       = (float*)d_out;
    float* agg_users = out;                          // [NUM_USERS, DIM]
    float* agg_items = out + NUM_USERS * DIM;        // [NUM_ITEMS, DIM]

    // Zero outputs (poisoned by harness).
    const int n4 = (NUM_USERS + NUM_ITEMS) * DIM / 4;
    zero_kernel<<<(n4 + 255) / 256, 256>>>((float4*)out, n4);

    // 8192 blocks x 256 threads = 131072 edge-groups; ~31 edges per group.
    lightgcn_edge_kernel<<<8192, 256>>>(user_emb, item_emb, edge_norm,
                                        u_idx, i_idx, agg_users, agg_items);
}

// round 2
// speedup vs baseline: 1.1305x; 1.1305x over previous
#include <cuda_runtime.h>

#define NUM_USERS 100000
#define NUM_ITEMS 50000
#define NUM_EDGES 4000000
#define DIM      64
#define NDEST    (NUM_ITEMS + NUM_USERS)      // items first, then users
#define NREC     (2 * NUM_EDGES)              // 8M records total
#define SCAN_BLK 1024
#define NSCANBLK ((NDEST + SCAN_BLK - 1) / SCAN_BLK)   // 147

// ---------------------------------------------------------------------------
// Scratch (static __device__ arrays — the allowed alternative to cudaMalloc).
// ---------------------------------------------------------------------------
__device__ int                d_cnt[NDEST];
__device__ int                d_off[NDEST];      // CSR offsets (exclusive scan)
__device__ int                d_pos[NDEST];      // working copy for scatter
__device__ int                d_bsum[NSCANBLK];
__device__ unsigned long long d_recs[NREC];      // packed (norm<<32 | src_idx)

// ---------------------------------------------------------------------------
// 1. zero counters
// ---------------------------------------------------------------------------
__global__ void k_zero_cnt() {
    int i = blockIdx.x * blockDim.x + threadIdx.x;
    if (i < NDEST) d_cnt[i] = 0;
}

// ---------------------------------------------------------------------------
// 2. histogram of destinations (both directions)
// ---------------------------------------------------------------------------
__global__ void __launch_bounds__(256)
k_hist(const int* __restrict__ u_idx, const int* __restrict__ i_idx) {
    int stride = gridDim.x * blockDim.x;
    for (int e = blockIdx.x * blockDim.x + threadIdx.x; e < NUM_EDGES; e += stride) {
        atomicAdd(&d_cnt[i_idx[e]], 1);              // item destination
        atomicAdd(&d_cnt[NUM_ITEMS + u_idx[e]], 1);  // user destination
    }
}

// ---------------------------------------------------------------------------
// 3a. per-block exclusive scan of d_cnt -> d_off, block totals -> d_bsum
// ---------------------------------------------------------------------------
__global__ void __launch_bounds__(SCAN_BLK)
k_scan1() {
    int gid  = blockIdx.x * SCAN_BLK + threadIdx.x;
    int lane = threadIdx.x & 31;
    int wid  = threadIdx.x >> 5;
    int v = (gid < NDEST) ? d_cnt[gid] : 0;

    // warp inclusive scan
    int x = v;
    #pragma unroll
    for (int o = 1; o < 32; o <<= 1) {
        int y = __shfl_up_sync(0xffffffffu, x, o);
        if (lane >= o) x += y;
    }
    __shared__ int wsum[32];
    if (lane == 31) wsum[wid] = x;
    __syncthreads();
    if (threadIdx.x < 32) {
        int w = wsum[threadIdx.x];
        #pragma unroll
        for (int o = 1; o < 32; o <<= 1) {
            int y = __shfl_up_sync(0xffffffffu, w, o);
            if (threadIdx.x >= o) w += y;
        }
        wsum[threadIdx.x] = w;
    }
    __syncthreads();
    int incl = x + (wid > 0 ? wsum[wid - 1] : 0);
    if (gid < NDEST) d_off[gid] = incl - v;          // exclusive within block
    if (threadIdx.x == SCAN_BLK - 1) d_bsum[blockIdx.x] = incl;
}

// ---------------------------------------------------------------------------
// 3b. exclusive scan of the 147 block sums (single block)
// ---------------------------------------------------------------------------
__global__ void __launch_bounds__(256)
k_scan2() {
    int lane = threadIdx.x & 31;
    int wid  = threadIdx.x >> 5;
    int v = (threadIdx.x < NSCANBLK) ? d_bsum[threadIdx.x] : 0;
    int x = v;
    #pragma unroll
    for (int o = 1; o < 32; o <<= 1) {
        int y = __shfl_up_sync(0xffffffffu, x, o);
        if (lane >= o) x += y;
    }
    __shared__ int wsum[8];
    if (lane == 31) wsum[wid] = x;
    __syncthreads();
    if (threadIdx.x < 8) {
        int w = wsum[threadIdx.x];
        #pragma unroll
        for (int o = 1; o < 8; o <<= 1) {
            int y = __shfl_up_sync(0xffu, w, o);
            if (threadIdx.x >= o) w += y;
        }
        wsum[threadIdx.x] = w;
    }
    __syncthreads();
    int incl = x + (wid > 0 ? wsum[wid - 1] : 0);
    if (threadIdx.x < NSCANBLK) d_bsum[threadIdx.x] = incl - v;   // exclusive
}

// ---------------------------------------------------------------------------
// 3c. add block offsets; init scatter cursors
// ---------------------------------------------------------------------------
__global__ void __launch_bounds__(SCAN_BLK)
k_scan3() {
    int gid = blockIdx.x * SCAN_BLK + threadIdx.x;
    if (gid < NDEST) {
        int o = d_off[gid] + d_bsum[blockIdx.x];
        d_off[gid] = o;
        d_pos[gid] = o;
    }
}

// ---------------------------------------------------------------------------
// 4. scatter edges into CSR record arrays (payload = source idx + norm)
// ---------------------------------------------------------------------------
__global__ void __launch_bounds__(256)
k_scatter(const int* __restrict__ u_idx, const int* __restrict__ i_idx,
          const float* __restrict__ edge_norm) {
    int stride = gridDim.x * blockDim.x;
    for (int e = blockIdx.x * blockDim.x + threadIdx.x; e < NUM_EDGES; e += stride) {
        int   u = u_idx[e];
        int   i = i_idx[e];
        float n = edge_norm[e];
        unsigned long long nb = ((unsigned long long)__float_as_uint(n)) << 32;
        int p = atomicAdd(&d_pos[i], 1);
        d_recs[p] = nb | (unsigned int)u;            // item dest <- user src
        int q = atomicAdd(&d_pos[NUM_ITEMS + u], 1);
        d_recs[q] = nb | (unsigned int)i;            // user dest <- item src
    }
}

// ---------------------------------------------------------------------------
// 5. aggregate: one warp per destination row, register accumulation.
//    Lanes 0-15 and 16-31 process alternate edges; combine at the end.
// ---------------------------------------------------------------------------
__global__ void __launch_bounds__(256)
k_agg(const float4* __restrict__ user_emb, const float4* __restrict__ item_emb,
      float* __restrict__ agg_users, float* __restrict__ agg_items) {
    int warp = (blockIdx.x * blockDim.x + threadIdx.x) >> 5;
    if (warp >= NDEST) return;
    int lane = threadIdx.x & 31;
    int l16  = lane & 15;        // float4 slot within 256B row
    int sub  = lane >> 4;        // which half-warp

    int start = d_off[warp];
    int end   = (warp == NDEST - 1) ? NREC : d_off[warp + 1];

    const float4* src;
    float*        outrow;
    if (warp < NUM_ITEMS) { src = user_emb; outrow = agg_items + (size_t)warp * DIM; }
    else                  { src = item_emb; outrow = agg_users + (size_t)(warp - NUM_ITEMS) * DIM; }

    float4 acc = make_float4(0.f, 0.f, 0.f, 0.f);
    for (int e = start + sub; e < end; e += 2) {
        unsigned long long r = d_recs[e];            // broadcast within half-warp
        int   idx = (int)(r & 0xffffffffull);
        float n   = __uint_as_float((unsigned int)(r >> 32));
        float4 v  = src[idx * (DIM / 4) + l16];      // coalesced 256B row read
        acc.x = fmaf(n, v.x, acc.x);
        acc.y = fmaf(n, v.y, acc.y);
        acc.z = fmaf(n, v.z, acc.z);
        acc.w = fmaf(n, v.w, acc.w);
    }
    // combine the two half-warp partials
    acc.x += __shfl_xor_sync(0xffffffffu, acc.x, 16);
    acc.y += __shfl_xor_sync(0xffffffffu, acc.y, 16);
    acc.z += __shfl_xor_sync(0xffffffffu, acc.z, 16);
    acc.w += __shfl_xor_sync(0xffffffffu, acc.w, 16);
    if (sub == 0) ((float4*)outrow)[l16] = acc;      // every dest row written (covers poison)
}

// ---------------------------------------------------------------------------
extern "C" void kernel_launch(void* const* d_in, const int* in_sizes, int n_in,
                              void* d_out, int out_size) {
    const float4* user_emb  = (const float4*)d_in[0];
    const float4* item_emb  = (const float4*)d_in[1];
    const float*  edge_norm = (const float*)d_in[2];
    const int*    u_idx     = (const int*)d_in[3];
    const int*    i_idx     = (const int*)d_in[4];

    float* out       = (float*)d_out;
    float* agg_users = out;                           // [NUM_USERS, DIM]
    float* agg_items = out + (size_t)NUM_USERS * DIM; // [NUM_ITEMS, DIM]

    k_zero_cnt<<<(NDEST + 255) / 256, 256>>>();
    k_hist<<<1024, 256>>>(u_idx, i_idx);
    k_scan1<<<NSCANBLK, SCAN_BLK>>>();
    k_scan2<<<1, 256>>>();
    k_scan3<<<NSCANBLK, SCAN_BLK>>>();
    k_scatter<<<1024, 256>>>(u_idx, i_idx, edge_norm);
    // 150000 destination warps, 8 warps per block
    k_agg<<<(NDEST * 32 + 255) / 256, 256>>>(user_emb, item_emb, agg_users, agg_items);
}